// round 2
// baseline (speedup 1.0000x reference)
#include <cuda_runtime.h>

#define NC    32
#define NPAR  4
#define NCH   7
#define NVOX  884736        // 96*96*96
#define NB    2
#define TPB   256
#define VPT   8
#define TILE  (TPB*VPT)     // 2048
#define NBLKX (NVOX/TILE)   // 432 exact

// global accumulators (scratch): per sample
// g_f layout: [0..31] denomA, [32..63] inter, [64] ce, [65] vw, [66..69] inter_s, [70..73] tgt_s
__device__ float    g_f[NB][74];
__device__ int      g_sib[NB];
__device__ unsigned g_hist[NB][NC*NC];

__global__ void k_init() {
    int tid = blockIdx.x * blockDim.x + threadIdx.x;
    if (tid < NB*74) ((float*)g_f)[tid] = 0.f;
    if (tid < NB)    g_sib[tid] = 0;
    if (tid < NB*NC*NC) ((unsigned*)g_hist)[tid] = 0u;
}

__device__ __forceinline__ float wred(float v) {
#pragma unroll
    for (int o = 16; o > 0; o >>= 1) v += __shfl_xor_sync(0xffffffffu, v, o);
    return v;
}

__global__ __launch_bounds__(TPB, 2)
void k_main(const float* __restrict__ img, const int* __restrict__ tgt,
            const int* __restrict__ msk, float* __restrict__ pred_out)
{
    const int b   = blockIdx.y;
    const int tid = threadIdx.x;
    const int lane = tid & 31;

    __shared__ float sh_dA[NC], sh_in[NC];
    __shared__ float sh_misc[10];      // ce, vw, is[4], ts[4]
    __shared__ int   sh_sib;
    __shared__ unsigned sh_hist[NC*NC];
    __shared__ unsigned char sh_m[NC];

    for (int i = tid; i < NC*NC; i += TPB) sh_hist[i] = 0u;
    if (tid < NC) {
        sh_dA[tid] = 0.f; sh_in[tid] = 0.f;
        sh_m[tid] = (msk[b*NC + tid] != 0) ? 1 : 0;   // masks are int32
    }
    if (tid < 10) sh_misc[tid] = 0.f;
    if (tid == 0) sh_sib = 0;
    __syncthreads();

    const float* base = img + (size_t)b * NC * NVOX;
    const int*   tb   = tgt + (size_t)b * NVOX;
    float*       pb   = pred_out + (size_t)b * NVOX;

    float accA[NC], accI[NC];
#pragma unroll
    for (int c = 0; c < NC; c++) { accA[c] = 0.f; accI[c] = 0.f; }
    float a_ce = 0.f, a_vw = 0.f;
    float a_is[4] = {0,0,0,0};
    float a_ts[4] = {0,0,0,0};
    int   a_sib = 0;

    const int v0 = blockIdx.x * TILE + tid;

#pragma unroll 1
    for (int it = 0; it < VPT; it++) {
        const int v = v0 + it * TPB;
        const int y = tb[v];
        const bool valid = (y != 255);
        const int ys = valid ? y : 0;
        const int ypar = (ys >= NPAR) ? (ys - NPAR) / NCH : -1;

        // load all 32 logits (coalesced per channel), track max
        float x[NC];
        float m = -1e30f;
#pragma unroll
        for (int c = 0; c < NC; c++) {
            x[c] = base[(size_t)c * NVOX + v];
            m = fmaxf(m, x[c]);
        }

        // argmax over leaves 4..31 (first max wins -> strict >)
        int am = NPAR; float bmv = x[NPAR];
#pragma unroll
        for (int c = NPAR + 1; c < NC; c++)
            if (x[c] > bmv) { bmv = x[c]; am = c; }
        pb[v] = (float)am;

        // exp + Z, capture e[y], e[parent(y)]
        float Z = 0.f, ey = 0.f, ep = 0.f;
#pragma unroll
        for (int c = 0; c < NC; c++) {
            float e = __expf(x[c] - m);
            x[c] = e; Z += e;
            if (c == ys) ey = e;
            if (c < NPAR) { if (c == ypar) ep = e; }
        }
        const float es0 = x[4], es1 = x[11], es2 = x[18], es3 = x[25];
        const float invZ = __fdividef(1.f, Z);
        const float sc = valid ? invZ : 0.f;

        // per-class accumulation in registers (no shared atomics)
#pragma unroll
        for (int c = 0; c < NC; c++) {
            accA[c] += x[c] * sc;
            bool hit = (c == ys) || (c < NPAR && c == ypar);
            if (hit) accI[c] += x[c] * sc;
        }

        // cross-entropy (clipped log, masked)
        const float py = ey * invZ, pp = ep * invZ;
        float ce = (sh_m[ys] ? 1.f : 0.f) *
                   __logf(fminf(fmaxf(py, 1e-7f), 1.f - 1e-7f));
        if (ypar >= 0)
            ce += (sh_m[ypar] ? 1.f : 0.f) *
                  __logf(fminf(fmaxf(pp, 1e-7f), 1.f - 1e-7f));
        if (valid) {
            a_ce -= ce;
            a_vw += 1.f;
            atomicAdd(&sh_hist[am * NC + ys], 1u);
        }

        // sink dice terms
        const int ppar = (am - NPAR) / NCH;   // am in [4,31]
        const bool mp = (sh_m[am] != 0);
        const float pes[4] = {es0, es1, es2, es3};
#pragma unroll
        for (int si = 0; si < 4; si++) {
            const int s = NPAR + si * NCH;
            bool sib = ((ypar == si) && (ys != s)) ||
                       ((!mp) && (ppar == si) && (am != s));
            bool pm = (ppar == si);
            if (valid) {
                if (pm && !sib) { a_is[si] += pes[si] * invZ; a_ts[si] += 1.f; }
                if (sib) a_sib |= (1 << si);
            }
        }
    }

    // ---- block reduction ----
    // warp transpose-reduce of accA/accI: lane l ends with the class-l warp sum
#pragma unroll
    for (int w = 16; w >= 1; w >>= 1) {
#pragma unroll
        for (int i = 0; i < w; i++) {
            float sA = (lane & w) ? accA[i] : accA[i + w];
            float rA = __shfl_xor_sync(0xffffffffu, sA, w);
            accA[i] = ((lane & w) ? accA[i + w] : accA[i]) + rA;
            float sI = (lane & w) ? accI[i] : accI[i + w];
            float rI = __shfl_xor_sync(0xffffffffu, sI, w);
            accI[i] = ((lane & w) ? accI[i + w] : accI[i]) + rI;
        }
    }
    atomicAdd(&sh_dA[lane], accA[0]);
    atomicAdd(&sh_in[lane], accI[0]);

    float r0 = wred(a_ce), r1 = wred(a_vw);
    float ri0 = wred(a_is[0]), ri1 = wred(a_is[1]), ri2 = wred(a_is[2]), ri3 = wred(a_is[3]);
    float rt0 = wred(a_ts[0]), rt1 = wred(a_ts[1]), rt2 = wred(a_ts[2]), rt3 = wred(a_ts[3]);
    int rs = a_sib;
#pragma unroll
    for (int o = 16; o > 0; o >>= 1) rs |= __shfl_xor_sync(0xffffffffu, rs, o);
    if (lane == 0) {
        atomicAdd(&sh_misc[0], r0);  atomicAdd(&sh_misc[1], r1);
        atomicAdd(&sh_misc[2], ri0); atomicAdd(&sh_misc[3], ri1);
        atomicAdd(&sh_misc[4], ri2); atomicAdd(&sh_misc[5], ri3);
        atomicAdd(&sh_misc[6], rt0); atomicAdd(&sh_misc[7], rt1);
        atomicAdd(&sh_misc[8], rt2); atomicAdd(&sh_misc[9], rt3);
        if (rs) atomicOr(&sh_sib, rs);
    }
    __syncthreads();

    // ---- global accumulation ----
    if (tid < NC) {
        atomicAdd(&g_f[b][tid],      sh_dA[tid]);
        atomicAdd(&g_f[b][NC + tid], sh_in[tid]);
    }
    if (tid >= 64 && tid < 74) atomicAdd(&g_f[b][tid], sh_misc[tid - 64]);
    if (tid == 74 && sh_sib)   atomicOr(&g_sib[b], sh_sib);
    for (int i = tid; i < NC*NC; i += TPB) {
        unsigned h = sh_hist[i];
        if (h) atomicAdd(&g_hist[b][i], h);
    }
}

__global__ void k_fin(const int* __restrict__ msk, float* __restrict__ out)
{
    int tid = threadIdx.x;
    if (tid >= NB * NC) return;
    int b = tid / NC, c = tid % NC;

    // ---- confusion matrix for class c ----
    float mf = (msk[b*NC + c] != 0) ? 1.f : 0.f;
    int mem[8]; int nm;
    if (c < NPAR) { nm = 1 + NCH; mem[0] = c; for (int i = 0; i < NCH; i++) mem[1+i] = NPAR + c*NCH + i; }
    else          { nm = 1; mem[0] = c; }
    float tp = 0.f, rs = 0.f, cs = 0.f;
    for (int i = 0; i < nm; i++) {
        int l = mem[i];
        for (int j = 0; j < nm; j++) tp += (float)g_hist[b][l*NC + mem[j]];
        for (int t = 0; t < NC; t++) { rs += (float)g_hist[b][l*NC + t]; cs += (float)g_hist[b][t*NC + l]; }
    }
    float* cm = out + 6 + (size_t)(b*NC + c) * 3;
    cm[0] = tp * mf;
    cm[1] = (rs - tp) * mf;
    cm[2] = (cs - tp) * mf;

    // ---- losses (one thread per sample) ----
    if (c == 0) {
        float vw = g_f[b][65];
        float ce = g_f[b][64] / fmaxf(vw, 1.f);

        float dsum = 0.f, msum = 0.f;
        for (int cc = 0; cc < NC; cc++) {
            float mfc = (msk[b*NC + cc] != 0) ? 1.f : 0.f;
            float dB = 0.f;
            for (int l = 0; l < NC; l++) dB += (float)g_hist[b][l*NC + cc];
            if (cc < NPAR)
                for (int i = 0; i < NCH; i++) {
                    int ch = NPAR + cc*NCH + i;
                    for (int l = 0; l < NC; l++) dB += (float)g_hist[b][l*NC + ch];
                }
            float dc = 1.f - 2.f * g_f[b][NC + cc] / (g_f[b][cc] + dB + 1e-5f);
            dsum += dc * mfc; msum += mfc;
        }
        float dice = dsum / fmaxf(msum, 1.f);

        float sdsum = 0.f, cnt = 0.f;
        int sib = g_sib[b];
        for (int si = 0; si < 4; si++) {
            int s = NPAR + si * NCH;
            float d = 1.f - (2.f * g_f[b][66 + si] + 1e-5f) /
                            (g_f[b][s] + g_f[b][70 + si] + 1e-5f);
            float fl = ((sib >> si) & 1) ? 1.f : 0.f;
            sdsum += d * fl; cnt += fl;
        }
        float sink = (cnt > 0.f) ? 0.1f * (sdsum / fmaxf(cnt, 1.f)) : 0.f;
        out[b*3 + 0] = ce;
        out[b*3 + 1] = dice;
        out[b*3 + 2] = sink;
    }
}

extern "C" void kernel_launch(void* const* d_in, const int* in_sizes, int n_in,
                              void* d_out, int out_size)
{
    const float* img = (const float*)d_in[0];
    const int*   tgt = (const int*)d_in[1];
    const int*   msk = (const int*)d_in[2];
    float* out = (float*)d_out;

    k_init<<<8, 256>>>();
    k_main<<<dim3(NBLKX, NB), TPB>>>(img, tgt, msk, out + 6 + NB*NC*3);
    k_fin<<<1, NB*NC>>>(msk, out);
}

// round 3
// speedup vs baseline: 1.0210x; 1.0210x over previous
#include <cuda_runtime.h>

#define NC    32
#define NPAR  4
#define NCH   7
#define NVOX  884736        // 96*96*96
#define NB    2
#define TPB   256
#define VPT   8
#define TILE  (TPB*VPT)     // 2048
#define NBLKX (NVOX/TILE)   // 432 exact
#define NBLK  (NBLKX*NB)    // 864

// global accumulators (zero-initialized at module load; last block resets after use)
// g_f layout: [0..31] denomA, [32..63] inter, [64] ce, [65] vw, [66..69] inter_s, [70..73] tgt_s
__device__ float        g_f[NB][74];
__device__ int          g_sib[NB];
__device__ unsigned     g_hist[NB][NC*NC];
__device__ unsigned int g_count;

__device__ __forceinline__ float wred(float v) {
#pragma unroll
    for (int o = 16; o > 0; o >>= 1) v += __shfl_xor_sync(0xffffffffu, v, o);
    return v;
}

__global__ __launch_bounds__(TPB, 2)
void k_all(const float* __restrict__ img, const int* __restrict__ tgt,
           const int* __restrict__ msk, float* __restrict__ out)
{
    const int b    = blockIdx.y;
    const int tid  = threadIdx.x;
    const int lane = tid & 31;

    __shared__ float sh_dA[NC], sh_in[NC];
    __shared__ float sh_misc[10];      // ce, vw, is[4], ts[4]
    __shared__ int   sh_sib;
    __shared__ unsigned sh_hist[NC*NC];
    __shared__ float sh_mf[NC];
    __shared__ int   sh_last;

    for (int i = tid; i < NC*NC; i += TPB) sh_hist[i] = 0u;
    if (tid < NC) {
        sh_dA[tid] = 0.f; sh_in[tid] = 0.f;
        sh_mf[tid] = (msk[b*NC + tid] != 0) ? 1.f : 0.f;
    }
    if (tid < 10) sh_misc[tid] = 0.f;
    if (tid == 0) { sh_sib = 0; sh_last = 0; }
    __syncthreads();

    const float* base = img + (size_t)b * NC * NVOX;
    const int*   tb   = tgt + (size_t)b * NVOX;
    float*       pb   = out + 6 + NB*NC*3 + (size_t)b * NVOX;

    float accA[NC], accI[NC];
#pragma unroll
    for (int c = 0; c < NC; c++) { accA[c] = 0.f; accI[c] = 0.f; }
    float a_ce = 0.f, a_vw = 0.f;
    float a_is[4] = {0,0,0,0};
    float a_ts[4] = {0,0,0,0};
    int   a_sib = 0;

    const int v0 = blockIdx.x * TILE + tid;
    const float L10_LO = -16.11809565f;   // log(1e-7)
    const float L10_HI = -1.0000001e-7f;  // log(1 - 1e-7)

#pragma unroll 1
    for (int it = 0; it < VPT; it++) {
        const int v = v0 + it * TPB;
        const int y = tb[v];
        const bool valid = (y != 255);
        const int ys = valid ? y : 0;
        const int ypar = (ys >= NPAR) ? (ys - NPAR) / NCH : -1;
        const int tmask = valid ? ((1 << ys) | ((ypar >= 0) ? (1 << ypar) : 0)) : 0;

        // load all 32 logits (coalesced per channel), track max
        float x[NC];
        float m = -1e30f;
#pragma unroll
        for (int c = 0; c < NC; c++) {
            x[c] = base[(size_t)c * NVOX + v];
            m = fmaxf(m, x[c]);
        }

        // argmax over leaves 4..31 (first max wins -> strict >)
        int am = NPAR; float bmv = x[NPAR];
#pragma unroll
        for (int c = NPAR + 1; c < NC; c++)
            if (x[c] > bmv) { bmv = x[c]; am = c; }
        pb[v] = (float)am;

        // exp + Z
        float Z = 0.f;
#pragma unroll
        for (int c = 0; c < NC; c++) {
            float e = __expf(x[c] - m);
            x[c] = e; Z += e;
        }
        const float es0 = x[4], es1 = x[11], es2 = x[18], es3 = x[25];
        const float invZ = __fdividef(1.f, Z);
        const float sc = valid ? invZ : 0.f;
        const float lnZ = __logf(Z);

        // per-class accumulation in registers (no shared atomics)
#pragma unroll
        for (int c = 0; c < NC; c++) {
            float t = x[c] * sc;
            accA[c] += t;
            if (tmask & (1 << c)) accI[c] += t;
        }

        // cross-entropy via re-loaded logits (L1-hit): log p = (x - m) - lnZ, clamped
        {
            float xy = __ldg(base + (size_t)ys * NVOX + v);
            float lpy = fminf(fmaxf(xy - m - lnZ, L10_LO), L10_HI);
            float ce = sh_mf[ys] * lpy;
            if (ypar >= 0) {
                float xp = __ldg(base + (size_t)ypar * NVOX + v);
                float lpp = fminf(fmaxf(xp - m - lnZ, L10_LO), L10_HI);
                ce += sh_mf[ypar] * lpp;
            }
            if (valid) {
                a_ce -= ce;
                a_vw += 1.f;
                atomicAdd(&sh_hist[am * NC + ys], 1u);
            }
        }

        // sink dice terms
        const int ppar = (am - NPAR) / NCH;   // am in [4,31]
        const bool mp = (sh_mf[am] != 0.f);
        const float pes[4] = {es0, es1, es2, es3};
#pragma unroll
        for (int si = 0; si < 4; si++) {
            const int s = NPAR + si * NCH;
            bool sib = ((ypar == si) && (ys != s)) ||
                       ((!mp) && (ppar == si) && (am != s));
            bool pm = (ppar == si);
            if (valid) {
                if (pm && !sib) { a_is[si] += pes[si] * invZ; a_ts[si] += 1.f; }
                if (sib) a_sib |= (1 << si);
            }
        }
    }

    // ---- block reduction ----
    // warp transpose-reduce of accA/accI: lane l ends with the class-l warp sum
#pragma unroll
    for (int w = 16; w >= 1; w >>= 1) {
#pragma unroll
        for (int i = 0; i < w; i++) {
            float sA = (lane & w) ? accA[i] : accA[i + w];
            float rA = __shfl_xor_sync(0xffffffffu, sA, w);
            accA[i] = ((lane & w) ? accA[i + w] : accA[i]) + rA;
            float sI = (lane & w) ? accI[i] : accI[i + w];
            float rI = __shfl_xor_sync(0xffffffffu, sI, w);
            accI[i] = ((lane & w) ? accI[i + w] : accI[i]) + rI;
        }
    }
    atomicAdd(&sh_dA[lane], accA[0]);
    atomicAdd(&sh_in[lane], accI[0]);

    float r0 = wred(a_ce), r1 = wred(a_vw);
    float ri0 = wred(a_is[0]), ri1 = wred(a_is[1]), ri2 = wred(a_is[2]), ri3 = wred(a_is[3]);
    float rt0 = wred(a_ts[0]), rt1 = wred(a_ts[1]), rt2 = wred(a_ts[2]), rt3 = wred(a_ts[3]);
    int rs = a_sib;
#pragma unroll
    for (int o = 16; o > 0; o >>= 1) rs |= __shfl_xor_sync(0xffffffffu, rs, o);
    if (lane == 0) {
        atomicAdd(&sh_misc[0], r0);  atomicAdd(&sh_misc[1], r1);
        atomicAdd(&sh_misc[2], ri0); atomicAdd(&sh_misc[3], ri1);
        atomicAdd(&sh_misc[4], ri2); atomicAdd(&sh_misc[5], ri3);
        atomicAdd(&sh_misc[6], rt0); atomicAdd(&sh_misc[7], rt1);
        atomicAdd(&sh_misc[8], rt2); atomicAdd(&sh_misc[9], rt3);
        if (rs) atomicOr(&sh_sib, rs);
    }
    __syncthreads();

    // ---- global accumulation ----
    if (tid < NC) {
        atomicAdd(&g_f[b][tid],      sh_dA[tid]);
        atomicAdd(&g_f[b][NC + tid], sh_in[tid]);
    }
    if (tid >= 64 && tid < 74) atomicAdd(&g_f[b][tid], sh_misc[tid - 64]);
    if (tid == 74 && sh_sib)   atomicOr(&g_sib[b], sh_sib);
    for (int i = tid; i < NC*NC; i += TPB) {
        unsigned h = sh_hist[i];
        if (h) atomicAdd(&g_hist[b][i], h);
    }

    // ---- last-block finalization ----
    __threadfence();
    if (tid == 0) {
        unsigned prev = atomicAdd(&g_count, 1u);
        sh_last = (prev == (unsigned)(NBLK - 1)) ? 1 : 0;
    }
    __syncthreads();
    if (!sh_last) return;

    if (tid < NB * NC) {
        int bb = tid / NC, c = tid % NC;

        // confusion matrix for class c
        float mf = (msk[bb*NC + c] != 0) ? 1.f : 0.f;
        int mem[8]; int nm;
        if (c < NPAR) { nm = 1 + NCH; mem[0] = c; for (int i = 0; i < NCH; i++) mem[1+i] = NPAR + c*NCH + i; }
        else          { nm = 1; mem[0] = c; }
        float tp = 0.f, rsum = 0.f, csum = 0.f;
        for (int i = 0; i < nm; i++) {
            int l = mem[i];
            for (int j = 0; j < nm; j++) tp += (float)g_hist[bb][l*NC + mem[j]];
            for (int t = 0; t < NC; t++) { rsum += (float)g_hist[bb][l*NC + t]; csum += (float)g_hist[bb][t*NC + l]; }
        }
        float* cm = out + 6 + (size_t)(bb*NC + c) * 3;
        cm[0] = tp * mf;
        cm[1] = (rsum - tp) * mf;
        cm[2] = (csum - tp) * mf;

        // losses (one thread per sample)
        if (c == 0) {
            float vw = g_f[bb][65];
            float ce = g_f[bb][64] / fmaxf(vw, 1.f);

            float dsum = 0.f, msum = 0.f;
            for (int cc = 0; cc < NC; cc++) {
                float mfc = (msk[bb*NC + cc] != 0) ? 1.f : 0.f;
                float dB = 0.f;
                for (int l = 0; l < NC; l++) dB += (float)g_hist[bb][l*NC + cc];
                if (cc < NPAR)
                    for (int i = 0; i < NCH; i++) {
                        int ch = NPAR + cc*NCH + i;
                        for (int l = 0; l < NC; l++) dB += (float)g_hist[bb][l*NC + ch];
                    }
                float dc = 1.f - 2.f * g_f[bb][NC + cc] / (g_f[bb][cc] + dB + 1e-5f);
                dsum += dc * mfc; msum += mfc;
            }
            float dice = dsum / fmaxf(msum, 1.f);

            float sdsum = 0.f, cnt = 0.f;
            int sib = g_sib[bb];
            for (int si = 0; si < 4; si++) {
                int s = NPAR + si * NCH;
                float d = 1.f - (2.f * g_f[bb][66 + si] + 1e-5f) /
                                (g_f[bb][s] + g_f[bb][70 + si] + 1e-5f);
                float fl = ((sib >> si) & 1) ? 1.f : 0.f;
                sdsum += d * fl; cnt += fl;
            }
            float sink = (cnt > 0.f) ? 0.1f * (sdsum / fmaxf(cnt, 1.f)) : 0.f;
            out[bb*3 + 0] = ce;
            out[bb*3 + 1] = dice;
            out[bb*3 + 2] = sink;
        }
    }

    // reset accumulators for the next graph replay
    __syncthreads();
    if (tid < NB*74) ((float*)g_f)[tid] = 0.f;
    if (tid < NB)    g_sib[tid] = 0;
    for (int i = tid; i < NB*NC*NC; i += TPB) ((unsigned*)g_hist)[i] = 0u;
    __threadfence();
    if (tid == 0) g_count = 0u;
}

extern "C" void kernel_launch(void* const* d_in, const int* in_sizes, int n_in,
                              void* d_out, int out_size)
{
    const float* img = (const float*)d_in[0];
    const int*   tgt = (const int*)d_in[1];
    const int*   msk = (const int*)d_in[2];
    float* out = (float*)d_out;

    k_all<<<dim3(NBLKX, NB), TPB>>>(img, tgt, msk, out);
}